// round 1
// baseline (speedup 1.0000x reference)
#include <cuda_runtime.h>

typedef unsigned long long u64;

// ---------------- flat parameter buffer (float2-duplicated values) ----------
#define OFF_T    0      // 256 Pauli tensor coeffs
#define OFF_W1   256    // 32
#define OFF_B1   288    // 32
#define OFF_W2T  320    // 512  (W2 transposed: [j][k])
#define OFF_B2   832    // 16
#define OFF_W3T  848    // 128  (W3 transposed: [j][k])
#define OFF_B3   976    // 8
#define OFF_W4   984    // 8
#define OFF_B4   992    // 1
#define NPARAM   993

__device__ u64 gAll[NPARAM];

// ---------------- packed f32x2 helpers --------------------------------------
__device__ __forceinline__ u64 pk(float lo, float hi) {
    u64 r; asm("mov.b64 %0, {%1, %2};" : "=l"(r) : "f"(lo), "f"(hi)); return r;
}
__device__ __forceinline__ void upk(float& lo, float& hi, u64 v) {
    asm("mov.b64 {%0, %1}, %2;" : "=f"(lo), "=f"(hi) : "l"(v));
}
__device__ __forceinline__ u64 fma2(u64 a, u64 b, u64 c) {
    u64 d; asm("fma.rn.f32x2 %0, %1, %2, %3;" : "=l"(d) : "l"(a), "l"(b), "l"(c));
    return d;
}
__device__ __forceinline__ u64 relu2(u64 v) {
    float a, b; upk(a, b, v);
    a = fmaxf(a, 0.f); b = fmaxf(b, 0.f);
    return pk(a, b);
}

// ---------------- precompute: U -> M -> Pauli tensor + weight dup -----------
__global__ void qnn_precompute(const float* __restrict__ qw,
                               const float* __restrict__ W1, const float* __restrict__ b1,
                               const float* __restrict__ W2, const float* __restrict__ b2,
                               const float* __restrict__ W3, const float* __restrict__ b3,
                               const float* __restrict__ W4, const float* __restrict__ b4) {
    __shared__ float2 Ucol[16][16];   // Ucol[j][m] = U[m][j]
    __shared__ float2 Msh[16][16];    // M[j][k]
    int tid = threadIdx.x;

    // Phase 1: 16 threads each evolve one basis column through the qw circuit
    if (tid < 16) {
        float2 st[16];
        for (int m = 0; m < 16; m++) { st[m].x = (m == tid) ? 1.f : 0.f; st[m].y = 0.f; }
        for (int layer = 0; layer < 2; layer++) {
            // RY then RZ per qubit
            for (int i = 0; i < 4; i++) {
                int str = 8 >> i;
                {   // RY(qw[layer*4+i])
                    float t = qw[layer * 4 + i];
                    float c = cosf(0.5f * t), s = sinf(0.5f * t);
                    for (int m = 0; m < 16; m++) if (!(m & str)) {
                        float2 a = st[m], b = st[m + str];
                        st[m].x       = c * a.x - s * b.x;  st[m].y       = c * a.y - s * b.y;
                        st[m + str].x = s * a.x + c * b.x;  st[m + str].y = s * a.y + c * b.y;
                    }
                }
                {   // RZ(qw[layer*4+i+4]): diag(e^{-it/2}, e^{+it/2})
                    float t = qw[layer * 4 + i + 4];
                    float cz = cosf(0.5f * t), sz = sinf(0.5f * t);
                    for (int m = 0; m < 16; m++) if (!(m & str)) {
                        float2 a = st[m], b = st[m + str];
                        st[m].x       = a.x * cz + a.y * sz;  st[m].y       = a.y * cz - a.x * sz;
                        st[m + str].x = b.x * cz - b.y * sz;  st[m + str].y = b.y * cz + b.x * sz;
                    }
                }
            }
            // CNOT perms in reference order: new[k] = old[p[k]]
            const int pc[6] = {0, 0, 0, 1, 1, 2};
            const int pt[6] = {1, 2, 3, 2, 3, 3};
            for (int pp = 0; pp < 6; pp++) {
                int c = pc[pp], tg = pt[pp];
                float2 tmp[16];
                for (int k = 0; k < 16; k++) {
                    int p = k ^ ((((unsigned)k >> (3 - c)) & 1u) << (3 - tg));
                    tmp[k] = st[p];
                }
                for (int k = 0; k < 16; k++) st[k] = tmp[k];
            }
            // RX per qubit
            for (int i = 0; i < 4; i++) {
                float t = qw[layer * 4 + i + 8];
                float c = cosf(0.5f * t), s = sinf(0.5f * t);
                int str = 8 >> i;
                for (int m = 0; m < 16; m++) if (!(m & str)) {
                    float2 a = st[m], b = st[m + str];
                    st[m].x       = c * a.x + s * b.y;  st[m].y       = c * a.y - s * b.x;
                    st[m + str].x = c * b.x + s * a.y;  st[m + str].y = c * b.y - s * a.x;
                }
            }
        }
        for (int m = 0; m < 16; m++) Ucol[tid][m] = st[m];
    }
    __syncthreads();

    // Phase 2: M[j][k] = sum_m conj(U[m][j]) * z_m * U[m][k]
    {
        int j = tid >> 4, k = tid & 15;
        float ar = 0.f, ai = 0.f;
        for (int m = 0; m < 16; m++) {
            float z = (m < 8) ? 1.f : -1.f;
            float2 uj = Ucol[j][m], uk = Ucol[k][m];
            ar += z * (uj.x * uk.x + uj.y * uk.y);
            ai += z * (uj.x * uk.y - uj.y * uk.x);
        }
        Msh[j][k].x = ar; Msh[j][k].y = ai;
    }
    __syncthreads();

    // Phase 3: Pauli coeffs c_a = Re(Tr(M P_a)) / 16
    {
        int a = tid;
        float accr = 0.f;
        for (int j = 0; j < 16; j++) {
            int k = j;
            float cr = 1.f, ci = 0.f;
            for (int i = 0; i < 4; i++) {
                int ai_ = (a >> (2 * (3 - i))) & 3;
                int ji  = (j >> (3 - i)) & 1;
                if (ai_ == 1) {            // X
                    k ^= (1 << (3 - i));
                } else if (ai_ == 2) {     // Y: *(+i) if j_i==0 else *(-i)
                    k ^= (1 << (3 - i));
                    float nr, ni;
                    if (ji == 0) { nr = -ci; ni = cr; } else { nr = ci; ni = -cr; }
                    cr = nr; ci = ni;
                } else if (ai_ == 3) {     // Z
                    if (ji) { cr = -cr; ci = -ci; }
                }
            }
            float2 m = Msh[j][k];
            accr += m.x * cr - m.y * ci;   // Re(M_{jk} * P_{kj})
        }
        float cv = accr * (1.0f / 16.0f);
        gAll[OFF_T + a] = pk(cv, cv);
    }

    // Phase 4: duplicated MLP weights
    for (int i = tid; i < 512; i += 256) {
        int j = i >> 4, k = i & 15;
        float w = W2[k * 32 + j];
        gAll[OFF_W2T + i] = pk(w, w);
    }
    for (int i = tid; i < 128; i += 256) {
        int j = i >> 3, k = i & 7;
        float w = W3[k * 16 + j];
        gAll[OFF_W3T + i] = pk(w, w);
    }
    if (tid < 32) {
        float w = W1[tid]; gAll[OFF_W1 + tid] = pk(w, w);
        float bb = b1[tid]; gAll[OFF_B1 + tid] = pk(bb, bb);
    }
    if (tid < 16) { float bb = b2[tid]; gAll[OFF_B2 + tid] = pk(bb, bb); }
    if (tid < 8) {
        float bb = b3[tid]; gAll[OFF_B3 + tid] = pk(bb, bb);
        float w = W4[tid];  gAll[OFF_W4 + tid] = pk(w, w);
    }
    if (tid == 0) { float bb = b4[0]; gAll[OFF_B4] = pk(bb, bb); }
}

// ---------------- main kernel: 4 samples / thread, packed f32x2 -------------
__global__ void __launch_bounds__(256) qnn_main(const float4* __restrict__ x4,
                                                float4* __restrict__ out4) {
    __shared__ u64 sAll[NPARAM];
    for (int i = threadIdx.x; i < NPARAM; i += 256) sAll[i] = gAll[i];
    __syncthreads();

    int t = blockIdx.x * 256 + threadIdx.x;
    int base = t * 4;

    // Bloch components per pair/qubit: [X,Y,Z] = [sin^2, -sin*cos, cos]
    u64 n[2][4][3];
#pragma unroll
    for (int p = 0; p < 2; p++) {
        float4 xa = x4[base + 2 * p];
        float4 xb = x4[base + 2 * p + 1];
        float va[4] = {xa.x, xa.y, xa.z, xa.w};
        float vb[4] = {xb.x, xb.y, xb.z, xb.w};
#pragma unroll
        for (int i = 0; i < 4; i++) {
            float sa, ca, sb, cb;
            __sincosf(va[i], &sa, &ca);
            __sincosf(vb[i], &sb, &cb);
            n[p][i][0] = pk(sa * sa, sb * sb);
            n[p][i][1] = pk(-sa * ca, -sb * cb);
            n[p][i][2] = pk(ca, cb);
        }
    }

    // q = Pauli tensor contraction (identity component == 1 is implicit)
    u64 q2[2];
    {
        u64 acc0[2];
#pragma unroll
        for (int a0 = 0; a0 < 4; a0++) {
            u64 acc1[2];
#pragma unroll
            for (int a1 = 0; a1 < 4; a1++) {
                u64 accA[2];
#pragma unroll
                for (int a2 = 0; a2 < 4; a2++) {
                    int bidx = ((a0 * 4 + a1) * 4 + a2) * 4;
                    u64 t0 = sAll[OFF_T + bidx];
                    u64 s3a = t0, s3b = t0;
#pragma unroll
                    for (int a3 = 1; a3 < 4; a3++) {
                        u64 tv = sAll[OFF_T + bidx + a3];
                        s3a = fma2(tv, n[0][3][a3 - 1], s3a);
                        s3b = fma2(tv, n[1][3][a3 - 1], s3b);
                    }
                    if (a2 == 0) { accA[0] = s3a; accA[1] = s3b; }
                    else {
                        accA[0] = fma2(s3a, n[0][2][a2 - 1], accA[0]);
                        accA[1] = fma2(s3b, n[1][2][a2 - 1], accA[1]);
                    }
                }
                if (a1 == 0) { acc1[0] = accA[0]; acc1[1] = accA[1]; }
                else {
                    acc1[0] = fma2(accA[0], n[0][1][a1 - 1], acc1[0]);
                    acc1[1] = fma2(accA[1], n[1][1][a1 - 1], acc1[1]);
                }
            }
            if (a0 == 0) { acc0[0] = acc1[0]; acc0[1] = acc1[1]; }
            else {
                acc0[0] = fma2(acc1[0], n[0][0][a0 - 1], acc0[0]);
                acc0[1] = fma2(acc1[1], n[1][0][a0 - 1], acc0[1]);
            }
        }
        q2[0] = acc0[0]; q2[1] = acc0[1];
    }

    // ---- MLP: 1 -> 32 -> 16 -> 8 -> 1 (layer fusion, j-outer) ----
    u64 a2acc[2][16];
#pragma unroll
    for (int k = 0; k < 16; k++) {
        u64 bb = sAll[OFF_B2 + k];
        a2acc[0][k] = bb; a2acc[1][k] = bb;
    }
#pragma unroll
    for (int j = 0; j < 32; j++) {
        u64 w = sAll[OFF_W1 + j], bb = sAll[OFF_B1 + j];
        u64 h0 = relu2(fma2(w, q2[0], bb));
        u64 h1 = relu2(fma2(w, q2[1], bb));
#pragma unroll
        for (int k = 0; k < 16; k++) {
            u64 ww = sAll[OFF_W2T + j * 16 + k];
            a2acc[0][k] = fma2(ww, h0, a2acc[0][k]);
            a2acc[1][k] = fma2(ww, h1, a2acc[1][k]);
        }
    }

    u64 a3acc[2][8];
#pragma unroll
    for (int k = 0; k < 8; k++) {
        u64 bb = sAll[OFF_B3 + k];
        a3acc[0][k] = bb; a3acc[1][k] = bb;
    }
#pragma unroll
    for (int j = 0; j < 16; j++) {
        u64 h0 = relu2(a2acc[0][j]);
        u64 h1 = relu2(a2acc[1][j]);
#pragma unroll
        for (int k = 0; k < 8; k++) {
            u64 ww = sAll[OFF_W3T + j * 8 + k];
            a3acc[0][k] = fma2(ww, h0, a3acc[0][k]);
            a3acc[1][k] = fma2(ww, h1, a3acc[1][k]);
        }
    }

    u64 o0 = sAll[OFF_B4], o1 = o0;
#pragma unroll
    for (int j = 0; j < 8; j++) {
        u64 h0 = relu2(a3acc[0][j]);
        u64 h1 = relu2(a3acc[1][j]);
        u64 ww = sAll[OFF_W4 + j];
        o0 = fma2(ww, h0, o0);
        o1 = fma2(ww, h1, o1);
    }

    float y0, y1, y2, y3;
    upk(y0, y1, o0);
    upk(y2, y3, o1);
    float4 r;
    r.x = __fdividef(1.f, 1.f + __expf(-y0));
    r.y = __fdividef(1.f, 1.f + __expf(-y1));
    r.z = __fdividef(1.f, 1.f + __expf(-y2));
    r.w = __fdividef(1.f, 1.f + __expf(-y3));
    out4[t] = r;
}

// ---------------- launch ----------------------------------------------------
extern "C" void kernel_launch(void* const* d_in, const int* in_sizes, int n_in,
                              void* d_out, int out_size) {
    const float* x  = (const float*)d_in[0];
    const float* qw = (const float*)d_in[1];
    const float* W1 = (const float*)d_in[2];
    const float* b1 = (const float*)d_in[3];
    const float* W2 = (const float*)d_in[4];
    const float* b2 = (const float*)d_in[5];
    const float* W3 = (const float*)d_in[6];
    const float* b3 = (const float*)d_in[7];
    const float* W4 = (const float*)d_in[8];
    const float* b4 = (const float*)d_in[9];

    qnn_precompute<<<1, 256>>>(qw, W1, b1, W2, b2, W3, b3, W4, b4);

    int nthreads = out_size / 4;           // 4 samples per thread
    qnn_main<<<nthreads / 256, 256>>>((const float4*)x, (float4*)d_out);
}

// round 2
// speedup vs baseline: 1.2478x; 1.2478x over previous
#include <cuda_runtime.h>

typedef unsigned long long u64;

#define TABN 4096

__device__ __align__(16) u64    gC[256];     // Pauli coeffs, duplicated (c,c)
__device__ __align__(16) float2 gTab[TABN];  // (value, slope) of sigmoid(MLP(q))

// ---------------- packed f32x2 helpers --------------------------------------
__device__ __forceinline__ u64 pk(float lo, float hi) {
    u64 r; asm("mov.b64 %0, {%1, %2};" : "=l"(r) : "f"(lo), "f"(hi)); return r;
}
__device__ __forceinline__ void upk(float& lo, float& hi, u64 v) {
    asm("mov.b64 {%0, %1}, %2;" : "=f"(lo), "=f"(hi) : "l"(v));
}
__device__ __forceinline__ u64 fma2(u64 a, u64 b, u64 c) {
    u64 d; asm("fma.rn.f32x2 %0, %1, %2, %3;" : "=l"(d) : "l"(a), "l"(b), "l"(c));
    return d;
}

// ---------------- scalar MLP eval (for table build) --------------------------
__device__ float mlp_eval(float q,
    const float* __restrict__ W1, const float* __restrict__ b1,
    const float* __restrict__ W2, const float* __restrict__ b2,
    const float* __restrict__ W3, const float* __restrict__ b3,
    const float* __restrict__ W4, const float* __restrict__ b4) {
    float h1[32];
#pragma unroll
    for (int j = 0; j < 32; j++) h1[j] = fmaxf(fmaf(W1[j], q, b1[j]), 0.f);
    float h2[16];
#pragma unroll
    for (int k = 0; k < 16; k++) {
        float s = b2[k];
#pragma unroll
        for (int j = 0; j < 32; j++) s = fmaf(W2[k * 32 + j], h1[j], s);
        h2[k] = fmaxf(s, 0.f);
    }
    float h3[8];
#pragma unroll
    for (int k = 0; k < 8; k++) {
        float s = b3[k];
#pragma unroll
        for (int j = 0; j < 16; j++) s = fmaf(W3[k * 16 + j], h2[j], s);
        h3[k] = fmaxf(s, 0.f);
    }
    float o = b4[0];
#pragma unroll
    for (int j = 0; j < 8; j++) o = fmaf(W4[j], h3[j], o);
    return 1.f / (1.f + expf(-o));
}

// ---------------- precompute: block 0 = Pauli coeffs; blocks 1..32 = table --
__global__ void qnn_pre(const float* __restrict__ qw,
                        const float* __restrict__ W1, const float* __restrict__ b1,
                        const float* __restrict__ W2, const float* __restrict__ b2,
                        const float* __restrict__ W3, const float* __restrict__ b3,
                        const float* __restrict__ W4, const float* __restrict__ b4) {
    int tid = threadIdx.x;

    if (blockIdx.x != 0) {
        // ---- table build: 32 blocks x 128 active threads -> 4096 entries ----
        if (tid < 128) {
            int i = (blockIdx.x - 1) * 128 + tid;
            float x0 = (float)i * (1.0f / 2048.0f) - 1.0f;
            float v0 = mlp_eval(x0, W1, b1, W2, b2, W3, b3, W4, b4);
            float v1 = mlp_eval(x0 + (1.0f / 2048.0f), W1, b1, W2, b2, W3, b3, W4, b4);
            gTab[i] = make_float2(v0, v1 - v0);
        }
        return;
    }

    // ---- block 0: U -> M -> Pauli tensor coeffs ----
    __shared__ float2 stS[16][17];
    __shared__ float2 Ucol[16][16];   // Ucol[j][m] = U[m][j]
    __shared__ float2 Msh[16][16];

    if (tid < 16) {
        float2* st = stS[tid];
        for (int m = 0; m < 16; m++) { st[m].x = (m == tid) ? 1.f : 0.f; st[m].y = 0.f; }
        for (int layer = 0; layer < 2; layer++) {
            for (int i = 0; i < 4; i++) {
                int str = 8 >> i;
                {   // RY
                    float t = qw[layer * 4 + i];
                    float c = cosf(0.5f * t), s = sinf(0.5f * t);
                    for (int m = 0; m < 16; m++) if (!(m & str)) {
                        float2 a = st[m], b = st[m + str];
                        st[m].x       = c * a.x - s * b.x;  st[m].y       = c * a.y - s * b.y;
                        st[m + str].x = s * a.x + c * b.x;  st[m + str].y = s * a.y + c * b.y;
                    }
                }
                {   // RZ
                    float t = qw[layer * 4 + i + 4];
                    float cz = cosf(0.5f * t), sz = sinf(0.5f * t);
                    for (int m = 0; m < 16; m++) if (!(m & str)) {
                        float2 a = st[m], b = st[m + str];
                        st[m].x       = a.x * cz + a.y * sz;  st[m].y       = a.y * cz - a.x * sz;
                        st[m + str].x = b.x * cz - b.y * sz;  st[m + str].y = b.y * cz + b.x * sz;
                    }
                }
            }
            // Composed permutation of the 6 CNOTs (reference order):
            // P[k]: a'=a, b'=b^a, c'=c^b^a, d'=d^c^b^a  (source index per dest k)
            {
                float2 tmp[16];
#pragma unroll
                for (int k = 0; k < 16; k++) {
                    int a = (k >> 3) & 1, b = (k >> 2) & 1, c = (k >> 1) & 1, d = k & 1;
                    int P = (a << 3) | ((b ^ a) << 2) | ((c ^ b ^ a) << 1) | (d ^ c ^ b ^ a);
                    tmp[k] = st[P];
                }
#pragma unroll
                for (int k = 0; k < 16; k++) st[k] = tmp[k];
            }
            // RX
            for (int i = 0; i < 4; i++) {
                float t = qw[layer * 4 + i + 8];
                float c = cosf(0.5f * t), s = sinf(0.5f * t);
                int str = 8 >> i;
                for (int m = 0; m < 16; m++) if (!(m & str)) {
                    float2 a = st[m], b = st[m + str];
                    st[m].x       = c * a.x + s * b.y;  st[m].y       = c * a.y - s * b.x;
                    st[m + str].x = c * b.x + s * a.y;  st[m + str].y = c * b.y - s * a.x;
                }
            }
        }
        for (int m = 0; m < 16; m++) Ucol[tid][m] = st[m];
    }
    __syncthreads();

    // M[j][k] = sum_m conj(U[m][j]) * z_m * U[m][k]
    {
        int j = tid >> 4, k = tid & 15;
        float ar = 0.f, ai = 0.f;
        for (int m = 0; m < 16; m++) {
            float z = (m < 8) ? 1.f : -1.f;
            float2 uj = Ucol[j][m], uk = Ucol[k][m];
            ar += z * (uj.x * uk.x + uj.y * uk.y);
            ai += z * (uj.x * uk.y - uj.y * uk.x);
        }
        Msh[j][k].x = ar; Msh[j][k].y = ai;
    }
    __syncthreads();

    // Pauli coeffs c_a = Re(Tr(M P_a)) / 16
    {
        int a = tid;
        float accr = 0.f;
        for (int j = 0; j < 16; j++) {
            int k = j;
            float cr = 1.f, ci = 0.f;
            for (int i = 0; i < 4; i++) {
                int ai_ = (a >> (2 * (3 - i))) & 3;
                int ji  = (j >> (3 - i)) & 1;
                if (ai_ == 1) {
                    k ^= (1 << (3 - i));
                } else if (ai_ == 2) {
                    k ^= (1 << (3 - i));
                    float nr, ni;
                    if (ji == 0) { nr = -ci; ni = cr; } else { nr = ci; ni = -cr; }
                    cr = nr; ci = ni;
                } else if (ai_ == 3) {
                    if (ji) { cr = -cr; ci = -ci; }
                }
            }
            float2 m = Msh[j][k];
            accr += m.x * cr - m.y * ci;
        }
        float cv = accr * (1.0f / 16.0f);
        gC[a] = pk(cv, cv);
    }
}

// ---------------- main kernel: 4 samples/thread, packed f32x2 + LUT ---------
__global__ void __launch_bounds__(128, 5) qnn_main(const float4* __restrict__ x4,
                                                   float4* __restrict__ out4) {
    __shared__ __align__(16) ulonglong2 sC[128];
    __shared__ __align__(16) float2 sTab[TABN];
    int tid = threadIdx.x;

    sC[tid] = ((const ulonglong2*)gC)[tid];
#pragma unroll
    for (int i = tid; i < TABN / 2; i += 128)
        ((float4*)sTab)[i] = ((const float4*)gTab)[i];
    __syncthreads();

    int t = blockIdx.x * 128 + tid;
    int base = t * 4;

    // Bloch components per pair/qubit: [X,Y,Z] = [sin^2, -sin*cos, cos]
    u64 n[2][4][3];
#pragma unroll
    for (int p = 0; p < 2; p++) {
        float4 xa = x4[base + 2 * p];
        float4 xb = x4[base + 2 * p + 1];
        float va[4] = {xa.x, xa.y, xa.z, xa.w};
        float vb[4] = {xb.x, xb.y, xb.z, xb.w};
#pragma unroll
        for (int i = 0; i < 4; i++) {
            float sa, ca, sb, cb;
            __sincosf(va[i], &sa, &ca);
            __sincosf(vb[i], &sb, &cb);
            n[p][i][0] = pk(sa * sa, sb * sb);
            n[p][i][1] = pk(-sa * ca, -sb * cb);
            n[p][i][2] = pk(ca, cb);
        }
    }

    // q = Pauli tensor contraction (identity component == 1 implicit)
    u64 Q0, Q1;
    {
        u64 acc0[2];
#pragma unroll
        for (int a0 = 0; a0 < 4; a0++) {
            u64 acc1[2];
#pragma unroll
            for (int a1 = 0; a1 < 4; a1++) {
                u64 accA[2];
#pragma unroll
                for (int a2 = 0; a2 < 4; a2++) {
                    int bidx = (a0 * 4 + a1) * 4 + a2;
                    ulonglong2 c01 = sC[2 * bidx];
                    ulonglong2 c23 = sC[2 * bidx + 1];
                    u64 s3a = fma2(c01.y, n[0][3][0], c01.x);
                    u64 s3b = fma2(c01.y, n[1][3][0], c01.x);
                    s3a = fma2(c23.x, n[0][3][1], s3a);
                    s3b = fma2(c23.x, n[1][3][1], s3b);
                    s3a = fma2(c23.y, n[0][3][2], s3a);
                    s3b = fma2(c23.y, n[1][3][2], s3b);
                    if (a2 == 0) { accA[0] = s3a; accA[1] = s3b; }
                    else {
                        accA[0] = fma2(s3a, n[0][2][a2 - 1], accA[0]);
                        accA[1] = fma2(s3b, n[1][2][a2 - 1], accA[1]);
                    }
                }
                if (a1 == 0) { acc1[0] = accA[0]; acc1[1] = accA[1]; }
                else {
                    acc1[0] = fma2(accA[0], n[0][1][a1 - 1], acc1[0]);
                    acc1[1] = fma2(accA[1], n[1][1][a1 - 1], acc1[1]);
                }
            }
            if (a0 == 0) { acc0[0] = acc1[0]; acc0[1] = acc1[1]; }
            else {
                acc0[0] = fma2(acc1[0], n[0][0][a0 - 1], acc0[0]);
                acc0[1] = fma2(acc1[1], n[1][0][a0 - 1], acc0[1]);
            }
        }
        Q0 = acc0[0]; Q1 = acc0[1];
    }

    // LUT lookup: out = sigmoid(MLP(q)) precomputed
    float q0, q1, q2v, q3;
    upk(q0, q1, Q0);
    upk(q2v, q3, Q1);

    float4 r;
    {
        float qs[4] = {q0, q1, q2v, q3};
        float rs[4];
#pragma unroll
        for (int s = 0; s < 4; s++) {
            float idxf = fmaf(qs[s], 2048.f, 2048.f);
            idxf = fminf(fmaxf(idxf, 0.f), 4095.9995f);
            float fi = floorf(idxf);
            int i = (int)fi;
            float fr = idxf - fi;
            float2 e = sTab[i];
            rs[s] = fmaf(e.y, fr, e.x);
        }
        r.x = rs[0]; r.y = rs[1]; r.z = rs[2]; r.w = rs[3];
    }
    out4[t] = r;
}

// ---------------- launch ----------------------------------------------------
extern "C" void kernel_launch(void* const* d_in, const int* in_sizes, int n_in,
                              void* d_out, int out_size) {
    const float* x  = (const float*)d_in[0];
    const float* qw = (const float*)d_in[1];
    const float* W1 = (const float*)d_in[2];
    const float* b1 = (const float*)d_in[3];
    const float* W2 = (const float*)d_in[4];
    const float* b2 = (const float*)d_in[5];
    const float* W3 = (const float*)d_in[6];
    const float* b3 = (const float*)d_in[7];
    const float* W4 = (const float*)d_in[8];
    const float* b4 = (const float*)d_in[9];

    qnn_pre<<<33, 256>>>(qw, W1, b1, W2, b2, W3, b3, W4, b4);

    int nthreads = out_size / 4;            // 4 samples per thread
    qnn_main<<<nthreads / 128, 128>>>((const float4*)x, (float4*)d_out);
}

// round 3
// speedup vs baseline: 1.2805x; 1.0262x over previous
#include <cuda_runtime.h>

typedef unsigned long long u64;

#define TABN 4096

__device__ __align__(16) u64    gC[256];     // Pauli coeffs, duplicated (c,c)
__device__ __align__(16) float2 gTab[TABN];  // (value, slope) of sigmoid(MLP(q))

// ---------------- packed f32x2 helpers --------------------------------------
__device__ __forceinline__ u64 pk(float lo, float hi) {
    u64 r; asm("mov.b64 %0, {%1, %2};" : "=l"(r) : "f"(lo), "f"(hi)); return r;
}
__device__ __forceinline__ void upk(float& lo, float& hi, u64 v) {
    asm("mov.b64 {%0, %1}, %2;" : "=f"(lo), "=f"(hi) : "l"(v));
}
__device__ __forceinline__ u64 fma2(u64 a, u64 b, u64 c) {
    u64 d; asm("fma.rn.f32x2 %0, %1, %2, %3;" : "=l"(d) : "l"(a), "l"(b), "l"(c));
    return d;
}

// ---------------- scalar MLP eval (for table build) --------------------------
__device__ float mlp_eval(float q,
    const float* __restrict__ W1, const float* __restrict__ b1,
    const float* __restrict__ W2, const float* __restrict__ b2,
    const float* __restrict__ W3, const float* __restrict__ b3,
    const float* __restrict__ W4, const float* __restrict__ b4) {
    float h1[32];
#pragma unroll
    for (int j = 0; j < 32; j++) h1[j] = fmaxf(fmaf(W1[j], q, b1[j]), 0.f);
    float h2[16];
#pragma unroll
    for (int k = 0; k < 16; k++) {
        float s = b2[k];
#pragma unroll
        for (int j = 0; j < 32; j++) s = fmaf(W2[k * 32 + j], h1[j], s);
        h2[k] = fmaxf(s, 0.f);
    }
    float h3[8];
#pragma unroll
    for (int k = 0; k < 8; k++) {
        float s = b3[k];
#pragma unroll
        for (int j = 0; j < 16; j++) s = fmaf(W3[k * 16 + j], h2[j], s);
        h3[k] = fmaxf(s, 0.f);
    }
    float o = b4[0];
#pragma unroll
    for (int j = 0; j < 8; j++) o = fmaf(W4[j], h3[j], o);
    return 1.f / (1.f + expf(-o));
}

// ---------------- precompute ------------------------------------------------
// Block 0: warp-shuffle circuit evolution -> M -> Pauli coeffs.
// Blocks 1..32: sigmoid(MLP(q)) table, 128 entries each.
__global__ void qnn_pre(const float* __restrict__ qw,
                        const float* __restrict__ W1, const float* __restrict__ b1,
                        const float* __restrict__ W2, const float* __restrict__ b2,
                        const float* __restrict__ W3, const float* __restrict__ b3,
                        const float* __restrict__ W4, const float* __restrict__ b4) {
    int tid = threadIdx.x;

    if (blockIdx.x != 0) {
        if (tid < 128) {
            int i = (blockIdx.x - 1) * 128 + tid;
            float x0 = (float)i * (1.0f / 2048.0f) - 1.0f;
            float v0 = mlp_eval(x0, W1, b1, W2, b2, W3, b3, W4, b4);
            float v1 = mlp_eval(x0 + (1.0f / 2048.0f), W1, b1, W2, b2, W3, b3, W4, b4);
            gTab[i] = make_float2(v0, v1 - v0);
        }
        return;
    }

    // ---- fully-parallel circuit: thread = (column j = tid>>4, amp m = tid&15)
    __shared__ float2 Ucol[16][16];   // Ucol[j][m] = U[m][j]
    __shared__ float2 Msh[16][16];

    {
        int j = tid >> 4, m = tid & 15;
        int lane = tid & 31;
        int laneHi = lane & 16;
        float re = (m == j) ? 1.f : 0.f;
        float im = 0.f;

        for (int layer = 0; layer < 2; layer++) {
#pragma unroll
            for (int i = 0; i < 4; i++) {
                int str = 8 >> i;
                int bit = m & str;
                {   // RY(qw[layer*4+i])
                    float t = qw[layer * 4 + i];
                    float c = cosf(0.5f * t), s = sinf(0.5f * t);
                    float pre = __shfl_xor_sync(0xffffffffu, re, str);
                    float pim = __shfl_xor_sync(0xffffffffu, im, str);
                    if (bit) { re = fmaf(s, pre, c * re); im = fmaf(s, pim, c * im); }
                    else     { re = fmaf(-s, pre, c * re); im = fmaf(-s, pim, c * im); }
                }
                {   // RZ(qw[layer*4+i+4])
                    float t = qw[layer * 4 + i + 4];
                    float cz = cosf(0.5f * t), sz = sinf(0.5f * t);
                    float nr, ni;
                    if (bit) { nr = re * cz - im * sz; ni = im * cz + re * sz; }
                    else     { nr = re * cz + im * sz; ni = im * cz - re * sz; }
                    re = nr; im = ni;
                }
            }
            // Composed CNOT permutation: src bits (a, b^a, c^b^a, d^c^b^a)
            {
                int a = (m >> 3) & 1, b = (m >> 2) & 1, c = (m >> 1) & 1, d = m & 1;
                int P = (a << 3) | ((b ^ a) << 2) | ((c ^ b ^ a) << 1) | (d ^ c ^ b ^ a);
                int srcLane = laneHi | P;
                re = __shfl_sync(0xffffffffu, re, srcLane);
                im = __shfl_sync(0xffffffffu, im, srcLane);
            }
#pragma unroll
            for (int i = 0; i < 4; i++) {   // RX(qw[layer*4+i+8])
                int str = 8 >> i;
                float t = qw[layer * 4 + i + 8];
                float c = cosf(0.5f * t), s = sinf(0.5f * t);
                float pre = __shfl_xor_sync(0xffffffffu, re, str);
                float pim = __shfl_xor_sync(0xffffffffu, im, str);
                float nr = fmaf(s, pim, c * re);
                float ni = fmaf(-s, pre, c * im);
                re = nr; im = ni;
            }
        }
        Ucol[j][m] = make_float2(re, im);
    }
    __syncthreads();

    // M[j][k] = sum_m conj(U[m][j]) * z_m * U[m][k]
    {
        int j = tid >> 4, k = tid & 15;
        float ar = 0.f, ai = 0.f;
        for (int m = 0; m < 16; m++) {
            float z = (m < 8) ? 1.f : -1.f;
            float2 uj = Ucol[j][m], uk = Ucol[k][m];
            ar += z * (uj.x * uk.x + uj.y * uk.y);
            ai += z * (uj.x * uk.y - uj.y * uk.x);
        }
        Msh[j][k] = make_float2(ar, ai);
    }
    __syncthreads();

    // Pauli coeffs c_a = Re(Tr(M P_a)) / 16
    {
        int a = tid;
        float accr = 0.f;
        for (int j = 0; j < 16; j++) {
            int k = j;
            float cr = 1.f, ci = 0.f;
            for (int i = 0; i < 4; i++) {
                int ai_ = (a >> (2 * (3 - i))) & 3;
                int ji  = (j >> (3 - i)) & 1;
                if (ai_ == 1) {
                    k ^= (1 << (3 - i));
                } else if (ai_ == 2) {
                    k ^= (1 << (3 - i));
                    float nr, ni;
                    if (ji == 0) { nr = -ci; ni = cr; } else { nr = ci; ni = -cr; }
                    cr = nr; ci = ni;
                } else if (ai_ == 3) {
                    if (ji) { cr = -cr; ci = -ci; }
                }
            }
            float2 mm = Msh[j][k];
            accr += mm.x * cr - mm.y * ci;
        }
        float cv = accr * (1.0f / 16.0f);
        gC[a] = pk(cv, cv);
    }
}

// ---------------- main kernel: 2 samples/thread, packed f32x2 + L1 LUT ------
__global__ void __launch_bounds__(128, 8) qnn_main(const float4* __restrict__ x4,
                                                   float2* __restrict__ out2) {
    __shared__ __align__(16) ulonglong2 sC[128];
    int tid = threadIdx.x;
    sC[tid] = ((const ulonglong2*)gC)[tid];
    __syncthreads();

    int t = blockIdx.x * 128 + tid;
    float4 xa = x4[2 * t];
    float4 xb = x4[2 * t + 1];

    // Bloch components per qubit: [X,Y,Z] = [sin^2, -sin*cos, cos]
    u64 n[4][3];
    {
        float va[4] = {xa.x, xa.y, xa.z, xa.w};
        float vb[4] = {xb.x, xb.y, xb.z, xb.w};
#pragma unroll
        for (int i = 0; i < 4; i++) {
            float sa, ca, sb, cb;
            __sincosf(va[i], &sa, &ca);
            __sincosf(vb[i], &sb, &cb);
            n[i][0] = pk(sa * sa, sb * sb);
            n[i][1] = pk(-sa * ca, -sb * cb);
            n[i][2] = pk(ca, cb);
        }
    }

    // q = Pauli tensor contraction (identity component == 1 implicit)
    u64 Q;
    {
        u64 acc0;
#pragma unroll
        for (int a0 = 0; a0 < 4; a0++) {
            u64 acc1;
#pragma unroll
            for (int a1 = 0; a1 < 4; a1++) {
                u64 accA;
#pragma unroll
                for (int a2 = 0; a2 < 4; a2++) {
                    int bidx = (a0 * 4 + a1) * 4 + a2;
                    ulonglong2 c01 = sC[2 * bidx];
                    ulonglong2 c23 = sC[2 * bidx + 1];
                    u64 s3 = fma2(c01.y, n[3][0], c01.x);
                    s3 = fma2(c23.x, n[3][1], s3);
                    s3 = fma2(c23.y, n[3][2], s3);
                    if (a2 == 0) accA = s3;
                    else         accA = fma2(s3, n[2][a2 - 1], accA);
                }
                if (a1 == 0) acc1 = accA;
                else         acc1 = fma2(accA, n[1][a1 - 1], acc1);
            }
            if (a0 == 0) acc0 = acc1;
            else         acc0 = fma2(acc1, n[0][a0 - 1], acc0);
        }
        Q = acc0;
    }

    float q0, q1;
    upk(q0, q1, Q);

    float2 r;
    {
        float qs[2] = {q0, q1};
        float rs[2];
#pragma unroll
        for (int s = 0; s < 2; s++) {
            float idxf = fmaf(qs[s], 2048.f, 2048.f);
            idxf = fminf(fmaxf(idxf, 0.f), 4095.9995f);
            float fi = floorf(idxf);
            int i = (int)fi;
            float fr = idxf - fi;
            float2 e = __ldg(&gTab[i]);
            rs[s] = fmaf(e.y, fr, e.x);
        }
        r.x = rs[0]; r.y = rs[1];
    }
    out2[t] = r;
}

// ---------------- launch ----------------------------------------------------
extern "C" void kernel_launch(void* const* d_in, const int* in_sizes, int n_in,
                              void* d_out, int out_size) {
    const float* x  = (const float*)d_in[0];
    const float* qw = (const float*)d_in[1];
    const float* W1 = (const float*)d_in[2];
    const float* b1 = (const float*)d_in[3];
    const float* W2 = (const float*)d_in[4];
    const float* b2 = (const float*)d_in[5];
    const float* W3 = (const float*)d_in[6];
    const float* b3 = (const float*)d_in[7];
    const float* W4 = (const float*)d_in[8];
    const float* b4 = (const float*)d_in[9];

    qnn_pre<<<33, 256>>>(qw, W1, b1, W2, b2, W3, b3, W4, b4);

    int nthreads = out_size / 2;             // 2 samples per thread
    qnn_main<<<nthreads / 128, 128>>>((const float4*)x, (float2*)d_out);
}